// round 16
// baseline (speedup 1.0000x reference)
#include <cuda_runtime.h>
#include <cuda_fp16.h>
#include <cstdint>

#define IC_   128
#define OC_   128
#define ZDIM_ 256
#define B_    16
#define WSIZE_ (OC_ * IC_ * 9)   // 147456

// Per-sample weights as fp16 in m16n8k16 A-fragment order:
// [b][chunk j=icc*9+tap (36)][tile (8)][kstep (2)][lane (32)][8 halves]
__device__ __half g_w[(size_t)B_ * WSIZE_];

__device__ __forceinline__ float to_tf32(float v) {
    float o;
    asm("cvt.rna.tf32.f32 %0, %1;" : "=f"(o) : "f"(v));
    return o;
}

__device__ __forceinline__ uint32_t smem_u32(const void* p) {
    uint32_t a;
    asm("{ .reg .u64 t; cvta.to.shared.u64 t, %1; cvt.u32.u64 %0, t; }" : "=r"(a) : "l"(p));
    return a;
}

__device__ __forceinline__ void cp_async16(uint32_t dst, const void* src) {
    asm volatile("cp.async.cg.shared.global [%0], [%1], 16;" :: "r"(dst), "l"(src));
}

__device__ __forceinline__ void mma_tf32(float* d, const uint32_t* a,
                                         uint32_t b0, uint32_t b1) {
    asm volatile(
        "mma.sync.aligned.m16n8k8.row.col.f32.tf32.tf32.f32 "
        "{%0,%1,%2,%3}, {%4,%5,%6,%7}, {%8,%9}, {%0,%1,%2,%3};"
        : "+f"(d[0]), "+f"(d[1]), "+f"(d[2]), "+f"(d[3])
        : "r"(a[0]), "r"(a[1]), "r"(a[2]), "r"(a[3]), "r"(b0), "r"(b1));
}

__device__ __forceinline__ void mma_f16(float* d, const uint4& a,
                                        uint32_t b0, uint32_t b1) {
    asm volatile(
        "mma.sync.aligned.m16n8k16.row.col.f32.f16.f16.f32 "
        "{%0,%1,%2,%3}, {%4,%5,%6,%7}, {%8,%9}, {%0,%1,%2,%3};"
        : "+f"(d[0]), "+f"(d[1]), "+f"(d[2]), "+f"(d[3])
        : "r"(a.x), "r"(a.y), "r"(a.z), "r"(a.w), "r"(b0), "r"(b1));
}

__device__ __forceinline__ void ldsm_x4(uint32_t* r, uint32_t addr) {
    asm volatile(
        "ldmatrix.sync.aligned.m8n8.x4.shared.b16 {%0,%1,%2,%3}, [%4];"
        : "=r"(r[0]), "=r"(r[1]), "=r"(r[2]), "=r"(r[3]) : "r"(addr));
}

// ---------------------------------------------------------------------------
// Kernel 1: per-sample weight generation on HMMA tf32, fp16 fragment output.
// (unchanged from R15)
// ---------------------------------------------------------------------------
#define WK_ZS_BYTES (ZDIM_ * 24 * 2)
#define WK_AST_FLOATS 576
#define WK_SM_BYTES (WK_ZS_BYTES + 8 * 2 * WK_AST_FLOATS * 4)

__global__ __launch_bounds__(256, 4) void weight_kernel(
    const float* __restrict__ z, const float* __restrict__ base_w,
    const float* __restrict__ head_w, const float* __restrict__ head_b)
{
    extern __shared__ char wsmc[];
    __half* zsh = reinterpret_cast<__half*>(wsmc);
    float*  Aw0 = reinterpret_cast<float*>(wsmc + WK_ZS_BYTES);

    const int tid = threadIdx.x;
    const int wid = tid >> 5;
    const int lid = tid & 31;
    const int g   = lid >> 2;
    const int tg  = lid & 3;

    const int bid    = blockIdx.x;
    const int tap    = bid % 9;
    const int t      = bid / 9;
    const int ichalf = t & 1;
    const int kstep  = (t >> 1) & 1;
    const int icc    = (t >> 2) & 3;
    const int tile   = t >> 4;

    const int ic = icc * 32 + kstep * 16 + ichalf * 8 + wid;
    const int m0 = (tile * 16) * 1152 + ic * 9 + tap;

    float* Awarp = Aw0 + wid * (2 * WK_AST_FLOATS);
    const uint32_t AwarpB = smem_u32(Awarp);

    auto cpA = [&](int kit, int stage) {
        uint32_t dstb = AwarpB + stage * (WK_AST_FLOATS * 4);
        const int c4 = lid & 7;
#pragma unroll
        for (int p = 0; p < 4; p++) {
            int row = (lid >> 3) + 4 * p;
            cp_async16(dstb + (row * 36 + c4 * 4) * 4,
                       head_w + (size_t)(m0 + row * 1152) * ZDIM_ + kit * 32 + c4 * 4);
        }
        asm volatile("cp.async.commit_group;" ::: "memory");
    };

    cpA(0, 0);
    cpA(1, 1);

    for (int i = tid; i < B_ * ZDIM_; i += 256) {
        int b = i >> 8;
        int d = i & 255;
        zsh[d * 24 + b] = __float2half_rn(z[i]);
    }

    float acc[2][4];
#pragma unroll
    for (int nt = 0; nt < 2; nt++)
#pragma unroll
        for (int r = 0; r < 4; r++) acc[nt][r] = 0.f;

    __syncthreads();

    for (int kit = 0; kit < 8; kit++) {
        if (kit < 7)
            asm volatile("cp.async.wait_group 1;" ::: "memory");
        else
            asm volatile("cp.async.wait_group 0;" ::: "memory");

        const float* As = Awarp + (kit & 1) * WK_AST_FLOATS;
#pragma unroll
        for (int ks = 0; ks < 4; ks++) {
            const int kl = ks * 8;
            uint32_t a[4];
            a[0] = __float_as_uint(to_tf32(As[g * 36 + kl + tg]));
            a[1] = __float_as_uint(to_tf32(As[(g + 8) * 36 + kl + tg]));
            a[2] = __float_as_uint(to_tf32(As[g * 36 + kl + tg + 4]));
            a[3] = __float_as_uint(to_tf32(As[(g + 8) * 36 + kl + tg + 4]));
            const int kg = kit * 32 + kl;
#pragma unroll
            for (int nt = 0; nt < 2; nt++) {
                uint32_t b0 = __float_as_uint(__half2float(zsh[(kg + tg) * 24 + g + 8 * nt]));
                uint32_t b1 = __float_as_uint(__half2float(zsh[(kg + tg + 4) * 24 + g + 8 * nt]));
                mma_tf32(acc[nt], a, b0, b1);
            }
        }

        if (kit + 2 < 8) cpA(kit + 2, kit & 1);
    }

    float bb[2];
#pragma unroll
    for (int r = 0; r < 2; r++) {
        int m = m0 + (g + 8 * r) * 1152;
        bb[r] = base_w[m] + head_b[m];
    }

    __syncthreads();
    __half* ob = reinterpret_cast<__half*>(Aw0);

    const int lane_o = g * 4 + (wid >> 1);
    const int hsel   = wid & 1;
#pragma unroll
    for (int nt = 0; nt < 2; nt++)
#pragma unroll
        for (int r = 0; r < 2; r++)
#pragma unroll
            for (int c = 0; c < 2; c++) {
                int b = 2 * tg + c + 8 * nt;
                ob[b * 128 + lane_o * 4 + r * 2 + hsel] =
                    __float2half_rn(bb[r] + acc[nt][r * 2 + c]);
            }
    __syncthreads();

    {
        const int jc = icc * 9 + tap;
#pragma unroll
        for (int e = 0; e < 2; e++) {
            int u    = tid * 2 + e;
            int b    = u >> 5;
            int lane = u & 31;
            const uint2 v = *reinterpret_cast<const uint2*>(&ob[b * 128 + lane * 4]);
            __half* dst = g_w + ((size_t)b * 36 + jc) * 4096 +
                          tile * 512 + kstep * 256 + lane * 8 + ichalf * 4;
            *reinterpret_cast<uint2*>(dst) = v;
        }
    }
}

// ---------------------------------------------------------------------------
// Kernel 2: implicit-GEMM conv, fp16 m16n8k16, ldmatrix B path.
// xsT[rowl 4][col 66][ic 40pad] halves: k-contiguous, so each B fragment row
// (8 k-halves at fixed n) is one 16B-aligned run; ldmatrix.x4 fetches both
// ksteps x both k-halves for one nt in one instruction (8 LDSM/chunk/warp).
// Row stride 80B -> all-32-bank conflict-free. Double-buffered xsT, builds
// overlapped; A per-warp 2-stage cp.async (unchanged).
// SMEM: A 32KB + 2 x 21120B = 75008 B.
// ---------------------------------------------------------------------------
#define XST_HALVES (4 * 66 * 40)                   // 10560 halves = 21120 B
#define XST_BYTES  (XST_HALVES * 2)
#define CONV_SMEM  (32768 + 2 * XST_BYTES)         // 75008

__global__ __launch_bounds__(256, 2) void conv_kernel(
    const float* __restrict__ x, float* __restrict__ out)
{
    extern __shared__ char smc[];
    const uint32_t smb = smem_u32(smc);

    const int tid  = threadIdx.x;
    const int wid  = tid >> 5;
    const int lid  = tid & 31;
    const int wm   = wid & 3;         // oc quarter (32 oc)
    const int wn   = wid >> 2;        // output row within pair
    const int pair = blockIdx.x;      // 0..31
    const int b    = blockIdx.y;      // 0..15
    const int r0   = pair * 2;

    const float* xb = x + (size_t)b * IC_ * 4096;
    const __half* wbase = g_w + (size_t)b * 36 * 4096;

    float acc[2][8][4];
#pragma unroll
    for (int mt = 0; mt < 2; mt++)
#pragma unroll
        for (int nt = 0; nt < 8; nt++)
#pragma unroll
            for (int r = 0; r < 4; r++) acc[mt][nt][r] = 0.f;

    auto xsh = [&](int q) {
        return reinterpret_cast<__half*>(smc + 32768 + q * XST_BYTES);
    };

    // build xsT[rr][col][ic]: col = pixel+1 (0..65), ic padded to 40.
    auto build_xs = [&](int icc, int q) {
        __half* xs = xsh(q);
        for (int idx = tid; idx < 1024; idx += 256) {
            int p2  = idx >> 6;               // ic pair 0..15
            int rem = idx & 63;
            int rr  = rem >> 4;               // 0..3
            int qd  = rem & 15;               // pixel quad
            int gr  = r0 - 1 + rr;
            float4 a0 = make_float4(0.f, 0.f, 0.f, 0.f);
            float4 a1 = a0;
            if ((unsigned)gr < 64u) {
                const float* xp = xb + (size_t)(icc * 32 + 2 * p2) * 4096 + gr * 64 + qd * 4;
                a0 = *reinterpret_cast<const float4*>(xp);
                a1 = *reinterpret_cast<const float4*>(xp + 4096);
            }
            __half* base = xs + rr * 2640 + (1 + qd * 4) * 40 + p2 * 2;
            *reinterpret_cast<__half2*>(base +   0) = __floats2half2_rn(a0.x, a1.x);
            *reinterpret_cast<__half2*>(base +  40) = __floats2half2_rn(a0.y, a1.y);
            *reinterpret_cast<__half2*>(base +  80) = __floats2half2_rn(a0.z, a1.z);
            *reinterpret_cast<__half2*>(base + 120) = __floats2half2_rn(a0.w, a1.w);
        }
        // borders col=0 and col=65 (pixel -1 / 64): always zero
        if (tid < 128) {
            int p2   = tid & 15;
            int rr   = (tid >> 4) & 3;
            int side = tid >> 6;
            *reinterpret_cast<__half2*>(xs + rr * 2640 + side * 65 * 40 + p2 * 2) =
                __half2half2(__float2half(0.f));
        }
    };

    // per-warp private A copy (unchanged)
    const uint32_t aw_dst0 = smb + wid * 4096 + lid * 16;
    auto cpA = [&](int j) {
        const __half* src = wbase + (size_t)j * 4096 + wm * 1024 + lid * 8;
        uint32_t dst = aw_dst0 + (j & 1) * 2048;
#pragma unroll
        for (int s = 0; s < 4; s++)
            cp_async16(dst + s * 512, src + s * 256);
        asm volatile("cp.async.commit_group;" ::: "memory");
    };

    // per-lane constant part of the ldmatrix address (bytes):
    //   row-within-tile = lid&7 -> n offset; tile = lid>>3 -> (kstep, khalf)
    const uint32_t ldsm_lane =
        (uint32_t)(((lid & 7) * 40 + (lid >> 4) * 16 + ((lid >> 3) & 1) * 8) * 2);

    auto mma_chunk = [&](int stage, int q, int kh, int kw) {
        const char* As = smc + wid * 4096 + stage * 2048 + lid * 16;
        uint4 a00 = *reinterpret_cast<const uint4*>(As);          // mt0 kstep0
        uint4 a01 = *reinterpret_cast<const uint4*>(As + 512);    // mt0 kstep1
        uint4 a10 = *reinterpret_cast<const uint4*>(As + 1024);   // mt1 kstep0
        uint4 a11 = *reinterpret_cast<const uint4*>(As + 1536);   // mt1 kstep1

        uint32_t addr0 = smb + 32768 + (uint32_t)q * XST_BYTES + ldsm_lane +
                         (uint32_t)(((wn + kh) * 2640 + kw * 40) * 2);

        uint32_t bq[2][4];
        ldsm_x4(bq[0], addr0);
#pragma unroll
        for (int nt = 0; nt < 8; nt++) {
            if (nt < 7) ldsm_x4(bq[(nt + 1) & 1], addr0 + (nt + 1) * 640);
            const uint32_t* cb = bq[nt & 1];
            mma_f16(acc[0][nt], a00, cb[0], cb[1]);
            mma_f16(acc[1][nt], a10, cb[0], cb[1]);
            mma_f16(acc[0][nt], a01, cb[2], cb[3]);
            mma_f16(acc[1][nt], a11, cb[2], cb[3]);
        }
    };

    // ---- prologue ----
    cpA(0);
    cpA(1);
    build_xs(0, 0);
    __syncthreads();

    // ---- main loop ----
    for (int icc = 0; icc < 4; icc++) {
        const int q = icc & 1;
#pragma unroll
        for (int tap = 0; tap < 9; tap++) {
            const int j  = icc * 9 + tap;
            const int kh = tap / 3;
            const int kw = tap - kh * 3;

            if (j < 34)
                asm volatile("cp.async.wait_group 1;" ::: "memory");
            else
                asm volatile("cp.async.wait_group 0;" ::: "memory");

            mma_chunk(j & 1, q, kh, kw);

            if (j + 2 < 36) cpA(j + 2);

            if (tap == 0 && icc < 3)
                build_xs(icc + 1, (icc + 1) & 1);
        }
        if (icc < 3)
            __syncthreads();
    }

    // ---- epilogue ----
    const int g  = lid >> 2;
    const int tg = lid & 3;
#pragma unroll
    for (int mt = 0; mt < 2; mt++) {
        int oc = wm * 32 + mt * 16 + g;
#pragma unroll
        for (int nt = 0; nt < 8; nt++) {
            int n  = wn * 64 + nt * 8 + 2 * tg;
            size_t base = ((size_t)b * OC_ + oc) * 4096 + pair * 128 + n;
            float2 v0 = make_float2(acc[mt][nt][0], acc[mt][nt][1]);
            float2 v1 = make_float2(acc[mt][nt][2], acc[mt][nt][3]);
            *reinterpret_cast<float2*>(out + base)            = v0;
            *reinterpret_cast<float2*>(out + base + 8 * 4096) = v1;
        }
    }
}

// ---------------------------------------------------------------------------
extern "C" void kernel_launch(void* const* d_in, const int* in_sizes, int n_in,
                              void* d_out, int out_size) {
    const float* x      = (const float*)d_in[0];
    const float* z      = (const float*)d_in[1];
    const float* base_w = (const float*)d_in[2];
    const float* head_w = (const float*)d_in[3];
    const float* head_b = (const float*)d_in[4];
    float* out = (float*)d_out;

    static bool attr_set = false;
    if (!attr_set) {
        cudaFuncSetAttribute(conv_kernel,
                             cudaFuncAttributeMaxDynamicSharedMemorySize,
                             CONV_SMEM);
        cudaFuncSetAttribute(weight_kernel,
                             cudaFuncAttributeMaxDynamicSharedMemorySize,
                             WK_SM_BYTES);
        attr_set = true;
    }

    weight_kernel<<<1152, 256, WK_SM_BYTES>>>(z, base_w, head_w, head_b);
    conv_kernel<<<dim3(32, 16), 256, CONV_SMEM>>>(x, out);
}